// round 10
// baseline (speedup 1.0000x reference)
#include <cuda_runtime.h>
#include <cstdint>

#define D      512
#define NCOLS  100000
#define BROWS  1000
#define NFILT  50
#define MPAD   1024
#define NPAD   100096        /* 1564*64 = 782*128 */

// quantization: x ~= QS*a + (QS/256)*b, a,b in [-127,127]
#define QS       (6.0f / 127.0f)
#define QS2      ((6.0f / 127.0f) * (6.0f / 127.0f))
#define INV_QS   (127.0f / 6.0f)
#define INV_QSB  (256.0f * 127.0f / 6.0f)

// ---------------- scratch (int8, K-major) ----------------
__device__ __align__(16) signed char g_qa[MPAD * D];
__device__ __align__(16) signed char g_qb[MPAD * D];
__device__ __align__(16) signed char g_ba[(size_t)NPAD * D];
__device__ __align__(16) signed char g_bb[(size_t)NPAD * D];
__device__ float g_T[BROWS];

// ---------------- helpers (sm_80-class PTX only) ----------------
__device__ __forceinline__ uint32_t smem_u32(const void* p) {
    uint32_t a;
    asm("{ .reg .u64 t; cvta.to.shared.u64 t, %1; cvt.u32.u64 %0, t; }" : "=r"(a) : "l"(p));
    return a;
}
__device__ __forceinline__ void cp16(uint32_t dst, const void* src) {
    asm volatile("cp.async.cg.shared.global [%0], [%1], 16;" :: "r"(dst), "l"(src));
}
__device__ __forceinline__ void ldm4(uint32_t* r, uint32_t a) {
    asm volatile("ldmatrix.sync.aligned.m8n8.x4.shared.b16 {%0,%1,%2,%3}, [%4];"
                 : "=r"(r[0]), "=r"(r[1]), "=r"(r[2]), "=r"(r[3]) : "r"(a));
}
__device__ __forceinline__ void imma(int* c, const uint32_t* a, uint32_t b0, uint32_t b1) {
    asm volatile("mma.sync.aligned.m16n8k32.row.col.s32.s8.s8.s32 "
                 "{%0,%1,%2,%3}, {%4,%5,%6,%7}, {%8,%9}, {%0,%1,%2,%3};"
                 : "+r"(c[0]), "+r"(c[1]), "+r"(c[2]), "+r"(c[3])
                 : "r"(a[0]), "r"(a[1]), "r"(a[2]), "r"(a[3]), "r"(b0), "r"(b1));
}
__device__ __forceinline__ int q8(float v, float scale) {
    int i = __float2int_rn(v * scale);
    return max(-127, min(127, i));
}
__device__ __forceinline__ uint32_t pack4(int a0, int a1, int a2, int a3) {
    return (uint32_t)(a0 & 255) | ((uint32_t)(a1 & 255) << 8) |
           ((uint32_t)(a2 & 255) << 16) | ((uint32_t)(a3 & 255) << 24);
}
// quantize 4 floats -> one a-word + one b-word
__device__ __forceinline__ void quant4(const float* x, uint32_t* aw, uint32_t* bw) {
    int a[4], b[4];
    #pragma unroll
    for (int i = 0; i < 4; i++) {
        a[i] = q8(x[i], INV_QS);
        float r = fmaf(-QS, (float)a[i], x[i]);
        b[i] = q8(r, INV_QSB);
    }
    *aw = pack4(a[0], a[1], a[2], a[3]);
    *bw = pack4(b[0], b[1], b[2], b[3]);
}

// ---------------------------------------------------------------------------
// convert q -> int8 a/b, padded to 1024 rows (pad rows zero)
// ---------------------------------------------------------------------------
__global__ void conv_q_kernel(const float* __restrict__ q) {
    int gid  = blockIdx.x * 256 + threadIdx.x;
    int base = gid * 8;
    if (base >= MPAD * D) return;
    int row = base >> 9;
    float x[8];
    if (row < BROWS) {
        float4 f0 = *(const float4*)(q + base);
        float4 f1 = *(const float4*)(q + base + 4);
        x[0]=f0.x; x[1]=f0.y; x[2]=f0.z; x[3]=f0.w;
        x[4]=f1.x; x[5]=f1.y; x[6]=f1.z; x[7]=f1.w;
    } else {
        #pragma unroll
        for (int i = 0; i < 8; i++) x[i] = 0.f;
    }
    uint32_t aw[2], bw[2];
    quant4(x, &aw[0], &bw[0]);
    quant4(x + 4, &aw[1], &bw[1]);
    *(uint2*)(g_qa + base) = make_uint2(aw[0], aw[1]);
    *(uint2*)(g_qb + base) = make_uint2(bw[0], bw[1]);
}

// ---------------------------------------------------------------------------
// transpose + quantize rhs[k][n] fp32 -> g_ba/g_bb [n][k] int8 (K-major)
// tile 64k x 128n, 256 threads
// ---------------------------------------------------------------------------
__global__ void __launch_bounds__(256)
conv_rhsT_kernel(const float* __restrict__ rhs) {
    __shared__ float st[128][68];
    int t  = threadIdx.x;
    int nb = blockIdx.x * 128;
    int kb = blockIdx.y * 64;

    int r  = t >> 5;
    int c4 = t & 31;
    int n0 = nb + c4 * 4;
    #pragma unroll
    for (int rr = 0; rr < 8; rr++) {
        int krow = rr * 8 + r;
        float4 v;
        const float* src = rhs + (size_t)(kb + krow) * NCOLS + n0;
        if (n0 + 3 < NCOLS) {
            v = *(const float4*)src;
        } else {
            v.x = (n0 + 0 < NCOLS) ? src[0] : 0.f;
            v.y = (n0 + 1 < NCOLS) ? src[1] : 0.f;
            v.z = (n0 + 2 < NCOLS) ? src[2] : 0.f;
            v.w = (n0 + 3 < NCOLS) ? src[3] : 0.f;
        }
        st[c4 * 4 + 0][krow] = v.x;
        st[c4 * 4 + 1][krow] = v.y;
        st[c4 * 4 + 2][krow] = v.z;
        st[c4 * 4 + 3][krow] = v.w;
    }
    __syncthreads();

    int n    = t >> 1;
    int koff = (t & 1) * 32;
    uint32_t aw[8], bw[8];
    #pragma unroll
    for (int jj = 0; jj < 8; jj++) {
        float x[4];
        *(float4*)x = *(const float4*)&st[n][koff + jj * 4];
        quant4(x, &aw[jj], &bw[jj]);
    }
    size_t o = (size_t)(nb + n) * D + kb + koff;
    *(uint4*)(g_ba + o)      = make_uint4(aw[0], aw[1], aw[2], aw[3]);
    *(uint4*)(g_ba + o + 16) = make_uint4(aw[4], aw[5], aw[6], aw[7]);
    *(uint4*)(g_bb + o)      = make_uint4(bw[0], bw[1], bw[2], bw[3]);
    *(uint4*)(g_bb + o + 16) = make_uint4(bw[4], bw[5], bw[6], bw[7]);
}

// ---------------------------------------------------------------------------
// prep: target score via dp4a on the SAME int8 arrays (exact int sums ->
// bit-identical to IMMA path), and out[b] = 1 - #(unique filtered >= t)
// ---------------------------------------------------------------------------
__global__ void __launch_bounds__(128)
prep_kernel(const int* __restrict__ fidx, const int* __restrict__ tgt,
            float* __restrict__ out) {
    int b = blockIdx.x;
    __shared__ int      list[NFILT + 1];
    __shared__ float    sv[NFILT + 1];
    __shared__ uint32_t qa[128], qb[128];
    int tid = threadIdx.x, wid = tid >> 5, lane = tid & 31;
    if (tid < 128) {
        qa[tid] = ((const uint32_t*)g_qa)[b * 128 + tid];
        qb[tid] = ((const uint32_t*)g_qb)[b * 128 + tid];
    }
    if (tid < NFILT)  list[tid]   = min(max(fidx[b * NFILT + tid], 0), NCOLS - 1);
    if (tid == NFILT) list[NFILT] = min(max(tgt[b], 0), NCOLS - 1);
    __syncthreads();
    for (int d = wid; d <= NFILT; d += 4) {
        int j = list[d];
        uint4 av = *(const uint4*)(g_ba + (size_t)j * D + lane * 16);
        uint4 bv = *(const uint4*)(g_bb + (size_t)j * D + lane * 16);
        uint32_t aW[4] = { av.x, av.y, av.z, av.w };
        uint32_t bW[4] = { bv.x, bv.y, bv.z, bv.w };
        int d1 = 0, dm = 0;
        #pragma unroll
        for (int w = 0; w < 4; w++) {
            uint32_t qaw = qa[lane * 4 + w], qbw = qb[lane * 4 + w];
            d1 = __dp4a((int)qaw, (int)aW[w], d1);
            dm = __dp4a((int)qaw, (int)bW[w], dm);
            dm = __dp4a((int)qbw, (int)aW[w], dm);
        }
        #pragma unroll
        for (int o = 16; o; o >>= 1) {
            d1 += __shfl_xor_sync(0xFFFFFFFFu, d1, o);
            dm += __shfl_xor_sync(0xFFFFFFFFu, dm, o);
        }
        if (lane == 0) sv[d] = QS2 * ((float)d1 + (float)dm * 0.00390625f);
    }
    __syncthreads();
    if (tid == 0) {
        float tv = sv[NFILT];
        g_T[b] = tv;
        float corr = 0.f;
        for (int i = 0; i <= NFILT; i++) {
            bool uniq = true;
            for (int jj = 0; jj < i; jj++)
                if (list[jj] == list[i]) { uniq = false; break; }
            if (uniq && sv[i] >= tv) corr += 1.f;
        }
        out[b] = 1.f - corr;
    }
}

// ---------------------------------------------------------------------------
// main GEMM (IMMA s8 m16n8k32, 3 passes: a*a -> d1, a*b + b*a -> d_mid)
// + fused rank count.  score = QS2*(d1 + d_mid/256)  (exact ints < 2^24)
// CTA 128m x 64n, 8 warps (4m x 2n), warp 32x32, OCCUPANCY 2.
// 2-stage cp.async pipeline, K=64/chunk, one barrier per chunk.
// smem rows: 64B data + 16B pad = 80B stride (conflict-free ldmatrix).
// ---------------------------------------------------------------------------
#define A_ARR      10240                   /* 128 rows * 80B, per a/b */
#define B_A_OFF    20480
#define B_B_OFF    30720
#define STG_BYTES  40960
#define SMEM_TOT   81920
#define NCHUNK     8

__global__ void __launch_bounds__(256, 2)
gemm_imma_kernel(float* __restrict__ out) {
    extern __shared__ char smem[];
    uint32_t sb = smem_u32(smem);
    const int tid = threadIdx.x, lane = tid & 31, wid = tid >> 5;
    const int warpM = wid & 3, warpN = wid >> 2;   // 4m x 2n
    const int mRow0 = blockIdx.x * 128;
    const int nBase = blockIdx.y * 64;

    int c1[2][4][4], cm[2][4][4];
    #pragma unroll
    for (int a = 0; a < 2; a++)
        #pragma unroll
        for (int b = 0; b < 4; b++)
            #pragma unroll
            for (int e = 0; e < 4; e++) { c1[a][b][e] = 0; cm[a][b][e] = 0; }

    auto load_chunk = [&](int ch, int slot) {
        uint32_t base = sb + slot * STG_BYTES;
        int k0 = ch * 64;
        #pragma unroll
        for (int i = 0; i < 2; i++) {                 // A a/b: 512 16B segs each
            int idx = tid + i * 256;
            int r = idx >> 2, seg = idx & 3;
            uint32_t dst = base + r * 80 + seg * 16;
            size_t go = (size_t)(mRow0 + r) * D + k0 + seg * 16;
            cp16(dst,         g_qa + go);
            cp16(dst + A_ARR, g_qb + go);
        }
        {                                             // B a/b: 256 16B segs each
            int r = tid >> 2, seg = tid & 3;
            uint32_t dst = base + B_A_OFF + r * 80 + seg * 16;
            size_t go = (size_t)(nBase + r) * D + k0 + seg * 16;
            cp16(dst,                       g_ba + go);
            cp16(dst + (B_B_OFF - B_A_OFF), g_bb + go);
        }
        asm volatile("cp.async.commit_group;" ::: "memory");
    };

    load_chunk(0, 0);

    for (int ch = 0; ch < NCHUNK; ch++) {
        asm volatile("cp.async.wait_group 0;" ::: "memory");
        __syncthreads();
        if (ch + 1 < NCHUNK) load_chunk(ch + 1, (ch + 1) & 1);

        uint32_t Ab = sb + (ch & 1) * STG_BYTES;
        #pragma unroll
        for (int s32 = 0; s32 < 2; s32++) {
            int kk = s32 * 32;
            // A fragments: m16k32 per mt; lanes: rows lane&15, +16B when lane>=16
            uint32_t AA[2][4], AB[2][4];
            {
                int arow  = lane & 15;
                int akoff = kk + ((lane >> 4) * 16);
                #pragma unroll
                for (int mt = 0; mt < 2; mt++) {
                    uint32_t addr = Ab + (warpM * 32 + mt * 16 + arow) * 80 + akoff;
                    ldm4(AA[mt], addr);
                    ldm4(AB[mt], addr + A_ARR);
                }
            }
            // B fragments: each ldm4 covers two n8 groups (n16) x k32
            uint32_t BA[2][4], BB[2][4];
            {
                int brow  = (lane & 7) + ((lane >> 4) & 1) * 8;
                int bkoff = kk + (((lane >> 3) & 1) * 16);
                #pragma unroll
                for (int g = 0; g < 2; g++) {
                    uint32_t addr = Ab + B_A_OFF + (warpN * 32 + g * 16 + brow) * 80 + bkoff;
                    ldm4(BA[g], addr);
                    ldm4(BB[g], addr + (B_B_OFF - B_A_OFF));
                }
            }
            // pass 1: a*a -> d1
            #pragma unroll
            for (int mt = 0; mt < 2; mt++)
                #pragma unroll
                for (int g = 0; g < 2; g++) {
                    imma(c1[mt][2 * g],     AA[mt], BA[g][0], BA[g][1]);
                    imma(c1[mt][2 * g + 1], AA[mt], BA[g][2], BA[g][3]);
                }
            // pass 2: a*b -> dm
            #pragma unroll
            for (int mt = 0; mt < 2; mt++)
                #pragma unroll
                for (int g = 0; g < 2; g++) {
                    imma(cm[mt][2 * g],     AA[mt], BB[g][0], BB[g][1]);
                    imma(cm[mt][2 * g + 1], AA[mt], BB[g][2], BB[g][3]);
                }
            // pass 3: b*a -> dm
            #pragma unroll
            for (int mt = 0; mt < 2; mt++)
                #pragma unroll
                for (int g = 0; g < 2; g++) {
                    imma(cm[mt][2 * g],     AB[mt], BA[g][0], BA[g][1]);
                    imma(cm[mt][2 * g + 1], AB[mt], BA[g][2], BA[g][3]);
                }
        }
    }

    // ---- epilogue: count s >= t per row ----
    #pragma unroll
    for (int mt = 0; mt < 2; mt++) {
        #pragma unroll
        for (int h = 0; h < 2; h++) {
            int row = mRow0 + warpM * 32 + mt * 16 + h * 8 + (lane >> 2);
            float tv = (row < BROWS) ? g_T[row] : 0.f;
            float cnt = 0.f;
            #pragma unroll
            for (int nt = 0; nt < 4; nt++) {
                int col = nBase + warpN * 32 + nt * 8 + (lane & 3) * 2;
                if (col < NCOLS) {   // NCOLS even -> col+1 also valid
                    float s0 = QS2 * ((float)c1[mt][nt][h * 2 + 0] +
                                      (float)cm[mt][nt][h * 2 + 0] * 0.00390625f);
                    float s1 = QS2 * ((float)c1[mt][nt][h * 2 + 1] +
                                      (float)cm[mt][nt][h * 2 + 1] * 0.00390625f);
                    if (s0 >= tv) cnt += 1.f;
                    if (s1 >= tv) cnt += 1.f;
                }
            }
            cnt += __shfl_xor_sync(0xFFFFFFFFu, cnt, 1);
            cnt += __shfl_xor_sync(0xFFFFFFFFu, cnt, 2);
            if ((lane & 3) == 0 && row < BROWS && cnt != 0.f)
                atomicAdd(out + row, cnt);
        }
    }
}

// ---------------------------------------------------------------------------
extern "C" void kernel_launch(void* const* d_in, const int* in_sizes, int n_in,
                              void* d_out, int out_size) {
    const float* q    = nullptr;
    const float* rhs  = nullptr;
    const int*   fidx = nullptr;
    const int*   tgt  = nullptr;
    for (int i = 0; i < n_in; i++) {
        switch (in_sizes[i]) {
            case BROWS * D:     q    = (const float*)d_in[i]; break;
            case D * NCOLS:     rhs  = (const float*)d_in[i]; break;
            case BROWS * NFILT: fidx = (const int*)d_in[i];   break;
            case BROWS:         tgt  = (const int*)d_in[i];   break;
        }
    }
    float* out = (float*)d_out;

    cudaFuncSetAttribute(gemm_imma_kernel,
                         cudaFuncAttributeMaxDynamicSharedMemorySize, SMEM_TOT);

    conv_q_kernel<<<256, 256>>>(q);
    conv_rhsT_kernel<<<dim3(NPAD / 128, D / 64), 256>>>(rhs);
    prep_kernel<<<BROWS, 128>>>(fidx, tgt, out);
    gemm_imma_kernel<<<dim3(MPAD / 128, NPAD / 64), 256, SMEM_TOT>>>(out);
}

// round 11
// speedup vs baseline: 2.0581x; 2.0581x over previous
#include <cuda_runtime.h>
#include <cuda_bf16.h>
#include <cstdint>

#define D      512
#define NCOLS  100000
#define BROWS  1000
#define NFILT  50
#define MPAD   1024
#define NPAD   100096        /* 782*128 */
#define NTILES 782
#define BAND   0.35f
#define GQCAP  (1 << 22)     /* 4.19M queue entries */
#define SQCAP  3584          /* smem staging entries (28KB <= stage smem) */

// ---------------- scratch ----------------
__device__ __align__(16) unsigned short g_qhi[MPAD * D];
__device__ __align__(16) unsigned short g_qlo[MPAD * D];
__device__ __align__(16) unsigned short g_bhi[(size_t)NPAD * D];   // [n][k] K-major
__device__ __align__(16) unsigned short g_blo[(size_t)NPAD * D];
__device__ float g_T[BROWS];
__device__ int   g_qcount;
__device__ uint32_t g_queue[2 * GQCAP];                            // {key, s2}

// ---------------- helpers (sm_80-class PTX only) ----------------
__device__ __forceinline__ uint32_t smem_u32(const void* p) {
    uint32_t a;
    asm("{ .reg .u64 t; cvta.to.shared.u64 t, %1; cvt.u32.u64 %0, t; }" : "=r"(a) : "l"(p));
    return a;
}
__device__ __forceinline__ void cp16(uint32_t dst, const void* src) {
    asm volatile("cp.async.cg.shared.global [%0], [%1], 16;" :: "r"(dst), "l"(src));
}
__device__ __forceinline__ void ldm4(uint32_t* r, uint32_t a) {
    asm volatile("ldmatrix.sync.aligned.m8n8.x4.shared.b16 {%0,%1,%2,%3}, [%4];"
                 : "=r"(r[0]), "=r"(r[1]), "=r"(r[2]), "=r"(r[3]) : "r"(a));
}
__device__ __forceinline__ void mma4(float* c, const uint32_t* a, uint32_t b0, uint32_t b1) {
    asm volatile("mma.sync.aligned.m16n8k16.row.col.f32.bf16.bf16.f32 "
                 "{%0,%1,%2,%3}, {%4,%5,%6,%7}, {%8,%9}, {%0,%1,%2,%3};"
                 : "+f"(c[0]), "+f"(c[1]), "+f"(c[2]), "+f"(c[3])
                 : "r"(a[0]), "r"(a[1]), "r"(a[2]), "r"(a[3]), "r"(b0), "r"(b1));
}
__device__ __forceinline__ void split4(const float* x, unsigned int* hiw, unsigned int* low) {
    #pragma unroll
    for (int p = 0; p < 2; p++) {
        unsigned int u0 = __float_as_uint(x[2 * p]);
        unsigned int u1 = __float_as_uint(x[2 * p + 1]);
        hiw[p] = __byte_perm(u0, u1, 0x7632);
        float h0 = __uint_as_float(u0 & 0xFFFF0000u);
        float h1 = __uint_as_float(u1 & 0xFFFF0000u);
        __nv_bfloat162 lp = __floats2bfloat162_rn(x[2 * p] - h0, x[2 * p + 1] - h1);
        low[p] = *(unsigned int*)&lp;
    }
}

// ---------------------------------------------------------------------------
// convert q -> hi/lo bf16, padded to 1024 rows; also resets the queue counter
// ---------------------------------------------------------------------------
__global__ void conv_q_kernel(const float* __restrict__ q) {
    int gid  = blockIdx.x * 256 + threadIdx.x;
    if (gid == 0) g_qcount = 0;
    int base = gid * 8;
    if (base >= MPAD * D) return;
    int row = base >> 9;
    float x[8];
    if (row < BROWS) {
        float4 f0 = *(const float4*)(q + base);
        float4 f1 = *(const float4*)(q + base + 4);
        x[0]=f0.x; x[1]=f0.y; x[2]=f0.z; x[3]=f0.w;
        x[4]=f1.x; x[5]=f1.y; x[6]=f1.z; x[7]=f1.w;
    } else {
        #pragma unroll
        for (int i = 0; i < 8; i++) x[i] = 0.f;
    }
    unsigned int hiw[4], low[4];
    split4(x, hiw, low);
    split4(x + 4, hiw + 2, low + 2);
    *(uint4*)(g_qhi + base) = make_uint4(hiw[0], hiw[1], hiw[2], hiw[3]);
    *(uint4*)(g_qlo + base) = make_uint4(low[0], low[1], low[2], low[3]);
}

// ---------------------------------------------------------------------------
// transpose + convert rhs[k][n] fp32 -> g_bhi/g_blo[n][k] bf16 (K-major)
// ---------------------------------------------------------------------------
__global__ void __launch_bounds__(256)
conv_rhsT_kernel(const float* __restrict__ rhs) {
    __shared__ float st[128][68];
    int t  = threadIdx.x;
    int nb = blockIdx.x * 128;
    int kb = blockIdx.y * 64;

    int r  = t >> 5;
    int c4 = t & 31;
    int n0 = nb + c4 * 4;
    #pragma unroll
    for (int rr = 0; rr < 8; rr++) {
        int krow = rr * 8 + r;
        float4 v;
        const float* src = rhs + (size_t)(kb + krow) * NCOLS + n0;
        if (n0 + 3 < NCOLS) {
            v = *(const float4*)src;
        } else {
            v.x = (n0 + 0 < NCOLS) ? src[0] : 0.f;
            v.y = (n0 + 1 < NCOLS) ? src[1] : 0.f;
            v.z = (n0 + 2 < NCOLS) ? src[2] : 0.f;
            v.w = (n0 + 3 < NCOLS) ? src[3] : 0.f;
        }
        st[c4 * 4 + 0][krow] = v.x;
        st[c4 * 4 + 1][krow] = v.y;
        st[c4 * 4 + 2][krow] = v.z;
        st[c4 * 4 + 3][krow] = v.w;
    }
    __syncthreads();

    int n    = t >> 1;
    int koff = (t & 1) * 32;
    unsigned int hiw[16], low[16];
    #pragma unroll
    for (int jj = 0; jj < 8; jj++) {
        float x[4];
        *(float4*)x = *(const float4*)&st[n][koff + jj * 4];
        split4(x, hiw + jj * 2, low + jj * 2);
    }
    size_t o = (size_t)(nb + n) * D + kb + koff;
    #pragma unroll
    for (int s = 0; s < 4; s++) {
        *(uint4*)(g_bhi + o + s * 8) = make_uint4(hiw[s*4], hiw[s*4+1], hiw[s*4+2], hiw[s*4+3]);
        *(uint4*)(g_blo + o + s * 8) = make_uint4(low[s*4], low[s*4+1], low[s*4+2], low[s*4+3]);
    }
}

// ---------------------------------------------------------------------------
// prep: target score t[b] (fp32 q x (b_hi+b_lo), contiguous reads) and
// out[b] = 1 - #(unique filtered j with s_j >= t)
// ---------------------------------------------------------------------------
__global__ void __launch_bounds__(128)
prep_kernel(const float* __restrict__ q,
            const int* __restrict__ fidx, const int* __restrict__ tgt,
            float* __restrict__ out) {
    int b = blockIdx.x;
    __shared__ int   list[NFILT + 1];
    __shared__ float sv[NFILT + 1];
    __shared__ float qs[D];
    int tid = threadIdx.x, wid = tid >> 5, lane = tid & 31;
    for (int k = tid; k < D; k += 128) qs[k] = q[b * D + k];
    if (tid < NFILT)  list[tid]   = min(max(fidx[b * NFILT + tid], 0), NCOLS - 1);
    if (tid == NFILT) list[NFILT] = min(max(tgt[b], 0), NCOLS - 1);
    __syncthreads();
    for (int d = wid; d <= NFILT; d += 4) {
        int j = list[d];
        const uint4* bh = (const uint4*)(g_bhi + (size_t)j * D);
        const uint4* bl = (const uint4*)(g_blo + (size_t)j * D);
        float acc = 0.f;
        #pragma unroll
        for (int v = 0; v < 2; v++) {
            uint4 h = bh[lane * 2 + v];
            uint4 l = bl[lane * 2 + v];
            unsigned int hw[4] = { h.x, h.y, h.z, h.w };
            unsigned int lw[4] = { l.x, l.y, l.z, l.w };
            int k0 = lane * 16 + v * 8;
            #pragma unroll
            for (int w = 0; w < 4; w++) {
                __nv_bfloat162 hb = *(__nv_bfloat162*)&hw[w];
                __nv_bfloat162 lb = *(__nv_bfloat162*)&lw[w];
                float b0 = __bfloat162float(hb.x) + __bfloat162float(lb.x);
                float b1 = __bfloat162float(hb.y) + __bfloat162float(lb.y);
                acc = fmaf(qs[k0 + w * 2 + 0], b0, acc);
                acc = fmaf(qs[k0 + w * 2 + 1], b1, acc);
            }
        }
        #pragma unroll
        for (int o = 16; o; o >>= 1) acc += __shfl_xor_sync(0xFFFFFFFFu, acc, o);
        if (lane == 0) sv[d] = acc;
    }
    __syncthreads();
    if (tid == 0) {
        float tv = sv[NFILT];
        g_T[b] = tv;
        float corr = 0.f;
        for (int i = 0; i <= NFILT; i++) {
            bool uniq = true;
            for (int jj = 0; jj < i; jj++)
                if (list[jj] == list[i]) { uniq = false; break; }
            if (uniq && sv[i] >= tv) corr += 1.f;
        }
        out[b] = 1.f - corr;
    }
}

// ---------------------------------------------------------------------------
// main GEMM: 2 passes only (hi*hi + hi*lo).  s2 = s_exact - q_lo.b_hi (+eps).
// Epilogue: s2 >= t+BAND -> count; |s2-t| < BAND -> queue for exact recheck.
// CTA 128m x 128n, 4 warps (2m x 2n), warp 64x64, occupancy 2, 2-stage
// cp.async, K=32/chunk. smem rows stride 80B (conflict-free ldmatrix).
// ---------------------------------------------------------------------------
#define A_BYTES    10240                    /* 128 rows * 80B (A hi only) */
#define B_OFF      A_BYTES
#define STG_BYTES  (3 * A_BYTES)            /* A_hi | B_hi | B_lo = 30720 */
#define SMEM_TOT   (2 * STG_BYTES)          /* 61440 */
#define NCHUNK     16

__global__ void __launch_bounds__(128, 2)
gemm_mma_kernel(float* __restrict__ out) {
    extern __shared__ char smem[];
    uint32_t sb = smem_u32(smem);
    const int tid = threadIdx.x, lane = tid & 31, wid = tid >> 5;
    const int warpM = wid & 1, warpN = wid >> 1;
    const int mRow0 = blockIdx.x * 128;
    const int nBase = blockIdx.y * 128;

    float c[4][8][4];
    #pragma unroll
    for (int a = 0; a < 4; a++)
        #pragma unroll
        for (int b = 0; b < 8; b++)
            #pragma unroll
            for (int e = 0; e < 4; e++) c[a][b][e] = 0.f;

    auto load_chunk = [&](int ch, int slot) {
        uint32_t base = sb + slot * STG_BYTES;
        int k0 = ch * 32;
        #pragma unroll
        for (int i = 0; i < 4; i++) {                 // A hi: 512 16B segs
            int idx = tid + i * 128;
            int r = idx >> 2, seg = idx & 3;
            uint32_t dst = base + r * 80 + seg * 16;
            cp16(dst, g_qhi + (size_t)(mRow0 + r) * D + k0 + seg * 8);
        }
        #pragma unroll
        for (int i = 0; i < 4; i++) {                 // B hi/lo: 512 segs each
            int idx = tid + i * 128;
            int r = idx >> 2, seg = idx & 3;
            uint32_t dst = base + B_OFF + r * 80 + seg * 16;
            size_t go = (size_t)(nBase + r) * D + k0 + seg * 8;
            cp16(dst,           g_bhi + go);
            cp16(dst + A_BYTES, g_blo + go);
        }
        asm volatile("cp.async.commit_group;" ::: "memory");
    };

    load_chunk(0, 0);

    for (int ch = 0; ch < NCHUNK; ch++) {
        asm volatile("cp.async.wait_group 0;" ::: "memory");
        __syncthreads();
        if (ch + 1 < NCHUNK) load_chunk(ch + 1, (ch + 1) & 1);

        uint32_t Ab = sb + (ch & 1) * STG_BYTES;
        uint32_t Bb = Ab + B_OFF;
        #pragma unroll
        for (int k16 = 0; k16 < 2; k16++) {
            uint32_t AH[4][4];
            {
                int ar  = warpM * 64 + ((lane >> 3) & 1) * 8 + (lane & 7);
                int aks = k16 * 2 + (lane >> 4);
                #pragma unroll
                for (int mt = 0; mt < 4; mt++)
                    ldm4(AH[mt], Ab + (ar + mt * 16) * 80 + aks * 16);
            }
            uint32_t BH[4][4], BL[4][4];
            {
                int brow  = warpN * 64 + ((lane >> 4) & 1) * 8 + (lane & 7);
                uint32_t boff = k16 * 32 + ((lane >> 3) & 1) * 16;
                #pragma unroll
                for (int nb = 0; nb < 4; nb++) {
                    uint32_t addr = Bb + (brow + nb * 16) * 80 + boff;
                    ldm4(BH[nb], addr);
                    ldm4(BL[nb], addr + A_BYTES);
                }
            }
            #pragma unroll
            for (int p = 0; p < 2; p++) {
                const uint32_t (*Bf)[4] = p ? BL : BH;
                #pragma unroll
                for (int mt = 0; mt < 4; mt++) {
                    #pragma unroll
                    for (int nb = 0; nb < 4; nb++) {
                        mma4(c[mt][2 * nb],     AH[mt], Bf[nb][0], Bf[nb][1]);
                        mma4(c[mt][2 * nb + 1], AH[mt], Bf[nb][2], Bf[nb][3]);
                    }
                }
            }
        }
    }

    // ---- epilogue: banded count + queue ----
    __syncthreads();                         // all smem reads done; reuse smem
    uint32_t* sq = (uint32_t*)smem;
    __shared__ int scnt;
    __shared__ int sbase;
    if (tid == 0) scnt = 0;
    __syncthreads();

    #pragma unroll
    for (int mt = 0; mt < 4; mt++) {
        #pragma unroll
        for (int h = 0; h < 2; h++) {
            int row = mRow0 + warpM * 64 + mt * 16 + h * 8 + (lane >> 2);
            if (row < BROWS) {
                float tv  = g_T[row];
                float tUp = tv + BAND, tDn = tv - BAND;
                float cnt = 0.f;
                #pragma unroll
                for (int nt = 0; nt < 8; nt++) {
                    int col = nBase + warpN * 64 + nt * 8 + (lane & 3) * 2;
                    #pragma unroll
                    for (int e = 0; e < 2; e++) {
                        int cc = col + e;
                        if (cc < NCOLS) {
                            float s2 = c[mt][nt][h * 2 + e];
                            if (s2 >= tUp) cnt += 1.f;
                            else if (s2 > tDn) {
                                uint32_t key = ((uint32_t)row << 17) | (uint32_t)cc;
                                int slot = atomicAdd(&scnt, 1);
                                if (slot < SQCAP) {
                                    sq[2 * slot]     = key;
                                    sq[2 * slot + 1] = __float_as_uint(s2);
                                } else {
                                    int g = atomicAdd(&g_qcount, 1);
                                    if (g < GQCAP) {
                                        g_queue[2 * g]     = key;
                                        g_queue[2 * g + 1] = __float_as_uint(s2);
                                    }
                                }
                            }
                        }
                    }
                }
                cnt += __shfl_xor_sync(0xFFFFFFFFu, cnt, 1);
                cnt += __shfl_xor_sync(0xFFFFFFFFu, cnt, 2);
                if ((lane & 3) == 0 && cnt != 0.f) atomicAdd(out + row, cnt);
            } else {
                __shfl_xor_sync(0xFFFFFFFFu, 0.f, 1);
                __shfl_xor_sync(0xFFFFFFFFu, 0.f, 2);
            }
        }
    }
    __syncthreads();
    if (tid == 0) {
        int n = min(scnt, SQCAP);
        sbase = (n > 0) ? atomicAdd(&g_qcount, n) : 0;
    }
    __syncthreads();
    int n = min(scnt, SQCAP);
    for (int i = tid; i < n; i += 128) {
        int g = sbase + i;
        if (g < GQCAP) {
            g_queue[2 * g]     = sq[2 * i];
            g_queue[2 * g + 1] = sq[2 * i + 1];
        }
    }
}

// ---------------------------------------------------------------------------
// recheck: s_refined = s2 + q_lo . b_hi  (warp per queue entry)
// ---------------------------------------------------------------------------
__global__ void __launch_bounds__(256)
recheck_kernel(float* __restrict__ out) {
    int gw   = (blockIdx.x * 256 + threadIdx.x) >> 5;
    int lane = threadIdx.x & 31;
    int total = g_qcount;
    if (total > GQCAP) total = GQCAP;
    int nw = gridDim.x * 8;
    for (int i = gw; i < total; i += nw) {
        uint32_t key = g_queue[2 * i];
        float s2 = __uint_as_float(g_queue[2 * i + 1]);
        int row = (int)(key >> 17), col = (int)(key & 0x1FFFFu);
        const uint4* ql = (const uint4*)(g_qlo + (size_t)row * D) + lane * 2;
        const uint4* bh = (const uint4*)(g_bhi + (size_t)col * D) + lane * 2;
        float d = 0.f;
        #pragma unroll
        for (int v = 0; v < 2; v++) {
            uint4 a = ql[v];
            uint4 b = bh[v];
            unsigned int aw[4] = { a.x, a.y, a.z, a.w };
            unsigned int bw[4] = { b.x, b.y, b.z, b.w };
            #pragma unroll
            for (int w = 0; w < 4; w++) {
                __nv_bfloat162 qa = *(__nv_bfloat162*)&aw[w];
                __nv_bfloat162 bb = *(__nv_bfloat162*)&bw[w];
                d = fmaf(__bfloat162float(qa.x), __bfloat162float(bb.x), d);
                d = fmaf(__bfloat162float(qa.y), __bfloat162float(bb.y), d);
            }
        }
        #pragma unroll
        for (int o = 16; o; o >>= 1) d += __shfl_xor_sync(0xFFFFFFFFu, d, o);
        if (lane == 0 && (s2 + d) >= g_T[row]) atomicAdd(out + row, 1.f);
    }
}

// ---------------------------------------------------------------------------
extern "C" void kernel_launch(void* const* d_in, const int* in_sizes, int n_in,
                              void* d_out, int out_size) {
    const float* q    = nullptr;
    const float* rhs  = nullptr;
    const int*   fidx = nullptr;
    const int*   tgt  = nullptr;
    for (int i = 0; i < n_in; i++) {
        switch (in_sizes[i]) {
            case BROWS * D:     q    = (const float*)d_in[i]; break;
            case D * NCOLS:     rhs  = (const float*)d_in[i]; break;
            case BROWS * NFILT: fidx = (const int*)d_in[i];   break;
            case BROWS:         tgt  = (const int*)d_in[i];   break;
        }
    }
    float* out = (float*)d_out;

    cudaFuncSetAttribute(gemm_mma_kernel,
                         cudaFuncAttributeMaxDynamicSharedMemorySize, SMEM_TOT);

    conv_q_kernel<<<256, 256>>>(q);
    conv_rhsT_kernel<<<dim3(NTILES, D / 64), 256>>>(rhs);
    prep_kernel<<<BROWS, 128>>>(q, fidx, tgt, out);
    gemm_mma_kernel<<<dim3(8, NTILES), 128, SMEM_TOT>>>(out);
    recheck_kernel<<<2048, 256>>>(out);
}

// round 12
// speedup vs baseline: 2.5350x; 1.2317x over previous
#include <cuda_runtime.h>
#include <cuda_bf16.h>
#include <cstdint>

#define D      512
#define NCOLS  100000
#define BROWS  1000
#define NFILT  50
#define MPAD   1024
#define NPAD   100096        /* 782*128 */
#define NTILES 782
#define BAND   0.3f
#define GQCAP  (1 << 22)
#define SQCAP  8192

// ---------------- scratch ----------------
__device__ __align__(16) unsigned short g_qhi[MPAD * D];
__device__ __align__(16) unsigned short g_qlo[MPAD * D];
__device__ __align__(16) unsigned short g_bhi[(size_t)NPAD * D];   // [n][k] K-major
__device__ __align__(16) unsigned short g_blo[(size_t)NPAD * D];
__device__ float g_T[BROWS];
__device__ int   g_qcount;
__device__ uint32_t g_queue[2 * GQCAP];                            // {key, s2}

// ---------------- helpers (sm_80-class PTX only) ----------------
__device__ __forceinline__ uint32_t smem_u32(const void* p) {
    uint32_t a;
    asm("{ .reg .u64 t; cvta.to.shared.u64 t, %1; cvt.u32.u64 %0, t; }" : "=r"(a) : "l"(p));
    return a;
}
__device__ __forceinline__ void cp16(uint32_t dst, const void* src) {
    asm volatile("cp.async.cg.shared.global [%0], [%1], 16;" :: "r"(dst), "l"(src));
}
__device__ __forceinline__ void ldm4(uint32_t* r, uint32_t a) {
    asm volatile("ldmatrix.sync.aligned.m8n8.x4.shared.b16 {%0,%1,%2,%3}, [%4];"
                 : "=r"(r[0]), "=r"(r[1]), "=r"(r[2]), "=r"(r[3]) : "r"(a));
}
__device__ __forceinline__ void mma4(float* c, const uint32_t* a, uint32_t b0, uint32_t b1) {
    asm volatile("mma.sync.aligned.m16n8k16.row.col.f32.bf16.bf16.f32 "
                 "{%0,%1,%2,%3}, {%4,%5,%6,%7}, {%8,%9}, {%0,%1,%2,%3};"
                 : "+f"(c[0]), "+f"(c[1]), "+f"(c[2]), "+f"(c[3])
                 : "r"(a[0]), "r"(a[1]), "r"(a[2]), "r"(a[3]), "r"(b0), "r"(b1));
}
__device__ __forceinline__ void split4(const float* x, unsigned int* hiw, unsigned int* low) {
    #pragma unroll
    for (int p = 0; p < 2; p++) {
        unsigned int u0 = __float_as_uint(x[2 * p]);
        unsigned int u1 = __float_as_uint(x[2 * p + 1]);
        hiw[p] = __byte_perm(u0, u1, 0x7632);
        float h0 = __uint_as_float(u0 & 0xFFFF0000u);
        float h1 = __uint_as_float(u1 & 0xFFFF0000u);
        __nv_bfloat162 lp = __floats2bfloat162_rn(x[2 * p] - h0, x[2 * p + 1] - h1);
        low[p] = *(unsigned int*)&lp;
    }
}

// ---------------------------------------------------------------------------
// convert q -> hi/lo bf16 (pad rows zero); resets queue counter
// ---------------------------------------------------------------------------
__global__ void conv_q_kernel(const float* __restrict__ q) {
    int gid  = blockIdx.x * 256 + threadIdx.x;
    if (gid == 0) g_qcount = 0;
    int base = gid * 8;
    if (base >= MPAD * D) return;
    int row = base >> 9;
    float x[8];
    if (row < BROWS) {
        float4 f0 = *(const float4*)(q + base);
        float4 f1 = *(const float4*)(q + base + 4);
        x[0]=f0.x; x[1]=f0.y; x[2]=f0.z; x[3]=f0.w;
        x[4]=f1.x; x[5]=f1.y; x[6]=f1.z; x[7]=f1.w;
    } else {
        #pragma unroll
        for (int i = 0; i < 8; i++) x[i] = 0.f;
    }
    unsigned int hiw[4], low[4];
    split4(x, hiw, low);
    split4(x + 4, hiw + 2, low + 2);
    *(uint4*)(g_qhi + base) = make_uint4(hiw[0], hiw[1], hiw[2], hiw[3]);
    *(uint4*)(g_qlo + base) = make_uint4(low[0], low[1], low[2], low[3]);
}

// ---------------------------------------------------------------------------
// transpose + convert rhs[k][n] fp32 -> g_bhi/g_blo[n][k] bf16 (K-major)
// ---------------------------------------------------------------------------
__global__ void __launch_bounds__(256)
conv_rhsT_kernel(const float* __restrict__ rhs) {
    __shared__ float st[128][68];
    int t  = threadIdx.x;
    int nb = blockIdx.x * 128;
    int kb = blockIdx.y * 64;

    int r  = t >> 5;
    int c4 = t & 31;
    int n0 = nb + c4 * 4;
    #pragma unroll
    for (int rr = 0; rr < 8; rr++) {
        int krow = rr * 8 + r;
        float4 v;
        const float* src = rhs + (size_t)(kb + krow) * NCOLS + n0;
        if (n0 + 3 < NCOLS) {
            v = *(const float4*)src;
        } else {
            v.x = (n0 + 0 < NCOLS) ? src[0] : 0.f;
            v.y = (n0 + 1 < NCOLS) ? src[1] : 0.f;
            v.z = (n0 + 2 < NCOLS) ? src[2] : 0.f;
            v.w = (n0 + 3 < NCOLS) ? src[3] : 0.f;
        }
        st[c4 * 4 + 0][krow] = v.x;
        st[c4 * 4 + 1][krow] = v.y;
        st[c4 * 4 + 2][krow] = v.z;
        st[c4 * 4 + 3][krow] = v.w;
    }
    __syncthreads();

    int n    = t >> 1;
    int koff = (t & 1) * 32;
    unsigned int hiw[16], low[16];
    #pragma unroll
    for (int jj = 0; jj < 8; jj++) {
        float x[4];
        *(float4*)x = *(const float4*)&st[n][koff + jj * 4];
        split4(x, hiw + jj * 2, low + jj * 2);
    }
    size_t o = (size_t)(nb + n) * D + kb + koff;
    #pragma unroll
    for (int s = 0; s < 4; s++) {
        *(uint4*)(g_bhi + o + s * 8) = make_uint4(hiw[s*4], hiw[s*4+1], hiw[s*4+2], hiw[s*4+3]);
        *(uint4*)(g_blo + o + s * 8) = make_uint4(low[s*4], low[s*4+1], low[s*4+2], low[s*4+3]);
    }
}

// ---------------------------------------------------------------------------
// prep: target score t[b] (fp32 q x (b_hi+b_lo), contiguous reads) and
// out[b] = 1 - #(unique filtered j with s_j >= t)
// ---------------------------------------------------------------------------
__global__ void __launch_bounds__(128)
prep_kernel(const float* __restrict__ q,
            const int* __restrict__ fidx, const int* __restrict__ tgt,
            float* __restrict__ out) {
    int b = blockIdx.x;
    __shared__ int   list[NFILT + 1];
    __shared__ float sv[NFILT + 1];
    __shared__ float qs[D];
    int tid = threadIdx.x, wid = tid >> 5, lane = tid & 31;
    for (int k = tid; k < D; k += 128) qs[k] = q[b * D + k];
    if (tid < NFILT)  list[tid]   = min(max(fidx[b * NFILT + tid], 0), NCOLS - 1);
    if (tid == NFILT) list[NFILT] = min(max(tgt[b], 0), NCOLS - 1);
    __syncthreads();
    for (int d = wid; d <= NFILT; d += 4) {
        int j = list[d];
        const uint4* bh = (const uint4*)(g_bhi + (size_t)j * D);
        const uint4* bl = (const uint4*)(g_blo + (size_t)j * D);
        float acc = 0.f;
        #pragma unroll
        for (int v = 0; v < 2; v++) {
            uint4 h = bh[lane * 2 + v];
            uint4 l = bl[lane * 2 + v];
            unsigned int hw[4] = { h.x, h.y, h.z, h.w };
            unsigned int lw[4] = { l.x, l.y, l.z, l.w };
            int k0 = lane * 16 + v * 8;
            #pragma unroll
            for (int w = 0; w < 4; w++) {
                __nv_bfloat162 hb = *(__nv_bfloat162*)&hw[w];
                __nv_bfloat162 lb = *(__nv_bfloat162*)&lw[w];
                float b0 = __bfloat162float(hb.x) + __bfloat162float(lb.x);
                float b1 = __bfloat162float(hb.y) + __bfloat162float(lb.y);
                acc = fmaf(qs[k0 + w * 2 + 0], b0, acc);
                acc = fmaf(qs[k0 + w * 2 + 1], b1, acc);
            }
        }
        #pragma unroll
        for (int o = 16; o; o >>= 1) acc += __shfl_xor_sync(0xFFFFFFFFu, acc, o);
        if (lane == 0) sv[d] = acc;
    }
    __syncthreads();
    if (tid == 0) {
        float tv = sv[NFILT];
        g_T[b] = tv;
        float corr = 0.f;
        for (int i = 0; i <= NFILT; i++) {
            bool uniq = true;
            for (int jj = 0; jj < i; jj++)
                if (list[jj] == list[i]) { uniq = false; break; }
            if (uniq && sv[i] >= tv) corr += 1.f;
        }
        out[b] = 1.f - corr;
    }
}

// ---------------------------------------------------------------------------
// main GEMM: 2 passes (hi*hi + hi*lo), s2 = s_exact - q_lo.b_hi (+eps).
// CTA 128m x 128n, 8 warps (4m x 2n), warp 32x64, OCCUPANCY 2.
// K-chunk 64 -> 8 chunks (half the barrier/wait events of K=32).
// smem rows: 128B data + 16B pad = 144B stride (r*36 mod 32 walk ->
// conflict-free ldmatrix). 2-stage cp.async; one barrier per chunk.
// Epilogue: s2 >= t+BAND -> count; |s2-t| < BAND -> queue for recheck.
// ---------------------------------------------------------------------------
#define A_BYTES    18432                    /* 128 rows * 144B (A hi only) */
#define B_OFF      A_BYTES
#define STG_BYTES  (3 * A_BYTES)            /* A_hi | B_hi | B_lo = 55296 */
#define SMEM_TOT   (2 * STG_BYTES)          /* 110592 */
#define NCHUNK     8

__global__ void __launch_bounds__(256, 2)
gemm_mma_kernel(float* __restrict__ out) {
    extern __shared__ char smem[];
    uint32_t sb = smem_u32(smem);
    const int tid = threadIdx.x, lane = tid & 31, wid = tid >> 5;
    const int warpM = wid & 3, warpN = wid >> 2;   // 4m x 2n
    const int mRow0 = blockIdx.x * 128;
    const int nBase = blockIdx.y * 128;

    float c[2][8][4];
    #pragma unroll
    for (int a = 0; a < 2; a++)
        #pragma unroll
        for (int b = 0; b < 8; b++)
            #pragma unroll
            for (int e = 0; e < 4; e++) c[a][b][e] = 0.f;

    auto load_chunk = [&](int ch, int slot) {
        uint32_t base = sb + slot * STG_BYTES;
        int k0 = ch * 64;
        #pragma unroll
        for (int i = 0; i < 4; i++) {                 // A hi: 1024 16B segs
            int idx = tid + i * 256;
            int r = idx >> 3, seg = idx & 7;
            uint32_t dst = base + r * 144 + seg * 16;
            cp16(dst, g_qhi + (size_t)(mRow0 + r) * D + k0 + seg * 8);
        }
        #pragma unroll
        for (int i = 0; i < 4; i++) {                 // B hi/lo: 1024 segs each
            int idx = tid + i * 256;
            int r = idx >> 3, seg = idx & 7;
            uint32_t dst = base + B_OFF + r * 144 + seg * 16;
            size_t go = (size_t)(nBase + r) * D + k0 + seg * 8;
            cp16(dst,           g_bhi + go);
            cp16(dst + A_BYTES, g_blo + go);
        }
        asm volatile("cp.async.commit_group;" ::: "memory");
    };

    load_chunk(0, 0);

    for (int ch = 0; ch < NCHUNK; ch++) {
        asm volatile("cp.async.wait_group 0;" ::: "memory");
        __syncthreads();
        if (ch + 1 < NCHUNK) load_chunk(ch + 1, (ch + 1) & 1);

        uint32_t Ab = sb + (ch & 1) * STG_BYTES;
        uint32_t Bb = Ab + B_OFF;
        #pragma unroll
        for (int k16 = 0; k16 < 4; k16++) {
            uint32_t AH[2][4];
            {
                int ar   = warpM * 32 + (lane & 15);
                int koff = k16 * 32 + (lane >> 4) * 16;
                #pragma unroll
                for (int mt = 0; mt < 2; mt++)
                    ldm4(AH[mt], Ab + (ar + mt * 16) * 144 + koff);
            }
            uint32_t BH[4][4], BL[4][4];
            {
                int brow  = warpN * 64 + ((lane >> 4) & 1) * 8 + (lane & 7);
                uint32_t boff = k16 * 32 + ((lane >> 3) & 1) * 16;
                #pragma unroll
                for (int nb = 0; nb < 4; nb++) {
                    uint32_t addr = Bb + (brow + nb * 16) * 144 + boff;
                    ldm4(BH[nb], addr);
                    ldm4(BL[nb], addr + A_BYTES);
                }
            }
            #pragma unroll
            for (int p = 0; p < 2; p++) {
                const uint32_t (*Bf)[4] = p ? BL : BH;
                #pragma unroll
                for (int mt = 0; mt < 2; mt++) {
                    #pragma unroll
                    for (int nb = 0; nb < 4; nb++) {
                        mma4(c[mt][2 * nb],     AH[mt], Bf[nb][0], Bf[nb][1]);
                        mma4(c[mt][2 * nb + 1], AH[mt], Bf[nb][2], Bf[nb][3]);
                    }
                }
            }
        }
    }

    // ---- epilogue: banded count + queue ----
    __syncthreads();                         // all smem reads done; reuse smem
    uint32_t* sq = (uint32_t*)smem;
    __shared__ int scnt;
    __shared__ int sbase;
    if (tid == 0) scnt = 0;
    __syncthreads();

    #pragma unroll
    for (int mt = 0; mt < 2; mt++) {
        #pragma unroll
        for (int h = 0; h < 2; h++) {
            int row = mRow0 + warpM * 32 + mt * 16 + h * 8 + (lane >> 2);
            if (row < BROWS) {
                float tv  = g_T[row];
                float tUp = tv + BAND, tDn = tv - BAND;
                float cnt = 0.f;
                #pragma unroll
                for (int nt = 0; nt < 8; nt++) {
                    int col = nBase + warpN * 64 + nt * 8 + (lane & 3) * 2;
                    #pragma unroll
                    for (int e = 0; e < 2; e++) {
                        int cc = col + e;
                        if (cc < NCOLS) {
                            float s2 = c[mt][nt][h * 2 + e];
                            if (s2 >= tUp) cnt += 1.f;
                            else if (s2 > tDn) {
                                uint32_t key = ((uint32_t)row << 17) | (uint32_t)cc;
                                int slot = atomicAdd(&scnt, 1);
                                if (slot < SQCAP) {
                                    sq[2 * slot]     = key;
                                    sq[2 * slot + 1] = __float_as_uint(s2);
                                } else {
                                    int g = atomicAdd(&g_qcount, 1);
                                    if (g < GQCAP) {
                                        g_queue[2 * g]     = key;
                                        g_queue[2 * g + 1] = __float_as_uint(s2);
                                    }
                                }
                            }
                        }
                    }
                }
                cnt += __shfl_xor_sync(0xFFFFFFFFu, cnt, 1);
                cnt += __shfl_xor_sync(0xFFFFFFFFu, cnt, 2);
                if ((lane & 3) == 0 && cnt != 0.f) atomicAdd(out + row, cnt);
            } else {
                __shfl_xor_sync(0xFFFFFFFFu, 0.f, 1);
                __shfl_xor_sync(0xFFFFFFFFu, 0.f, 2);
            }
        }
    }
    __syncthreads();
    if (tid == 0) {
        int n = min(scnt, SQCAP);
        sbase = (n > 0) ? atomicAdd(&g_qcount, n) : 0;
    }
    __syncthreads();
    int n = min(scnt, SQCAP);
    for (int i = tid; i < n; i += 256) {
        int g = sbase + i;
        if (g < GQCAP) {
            g_queue[2 * g]     = sq[2 * i];
            g_queue[2 * g + 1] = sq[2 * i + 1];
        }
    }
}

// ---------------------------------------------------------------------------
// recheck: s_refined = s2 + q_lo . b_hi  (warp per queue entry)
// ---------------------------------------------------------------------------
__global__ void __launch_bounds__(256)
recheck_kernel(float* __restrict__ out) {
    int gw   = (blockIdx.x * 256 + threadIdx.x) >> 5;
    int lane = threadIdx.x & 31;
    int total = g_qcount;
    if (total > GQCAP) total = GQCAP;
    int nw = gridDim.x * 8;
    for (int i = gw; i < total; i += nw) {
        uint32_t key = g_queue[2 * i];
        float s2 = __uint_as_float(g_queue[2 * i + 1]);
        int row = (int)(key >> 17), col = (int)(key & 0x1FFFFu);
        const uint4* ql = (const uint4*)(g_qlo + (size_t)row * D) + lane * 2;
        const uint4* bh = (const uint4*)(g_bhi + (size_t)col * D) + lane * 2;
        float d = 0.f;
        #pragma unroll
        for (int v = 0; v < 2; v++) {
            uint4 a = ql[v];
            uint4 b = bh[v];
            unsigned int aw[4] = { a.x, a.y, a.z, a.w };
            unsigned int bw[4] = { b.x, b.y, b.z, b.w };
            #pragma unroll
            for (int w = 0; w < 4; w++) {
                __nv_bfloat162 qa = *(__nv_bfloat162*)&aw[w];
                __nv_bfloat162 bb = *(__nv_bfloat162*)&bw[w];
                d = fmaf(__bfloat162float(qa.x), __bfloat162float(bb.x), d);
                d = fmaf(__bfloat162float(qa.y), __bfloat162float(bb.y), d);
            }
        }
        #pragma unroll
        for (int o = 16; o; o >>= 1) d += __shfl_xor_sync(0xFFFFFFFFu, d, o);
        if (lane == 0 && (s2 + d) >= g_T[row]) atomicAdd(out + row, 1.f);
    }
}

// ---------------------------------------------------------------------------
extern "C" void kernel_launch(void* const* d_in, const int* in_sizes, int n_in,
                              void* d_out, int out_size) {
    const float* q    = nullptr;
    const float* rhs  = nullptr;
    const int*   fidx = nullptr;
    const int*   tgt  = nullptr;
    for (int i = 0; i < n_in; i++) {
        switch (in_sizes[i]) {
            case BROWS * D:     q    = (const float*)d_in[i]; break;
            case D * NCOLS:     rhs  = (const float*)d_in[i]; break;
            case BROWS * NFILT: fidx = (const int*)d_in[i];   break;
            case BROWS:         tgt  = (const int*)d_in[i];   break;
        }
    }
    float* out = (float*)d_out;

    cudaFuncSetAttribute(gemm_mma_kernel,
                         cudaFuncAttributeMaxDynamicSharedMemorySize, SMEM_TOT);

    conv_q_kernel<<<256, 256>>>(q);
    conv_rhsT_kernel<<<dim3(NTILES, D / 64), 256>>>(rhs);
    prep_kernel<<<BROWS, 128>>>(q, fidx, tgt, out);
    gemm_mma_kernel<<<dim3(8, NTILES), 256, SMEM_TOT>>>(out);
    recheck_kernel<<<2048, 256>>>(out);
}

// round 13
// speedup vs baseline: 2.5904x; 1.0219x over previous
#include <cuda_runtime.h>
#include <cuda_bf16.h>
#include <cstdint>

#define D      512
#define NCOLS  100000
#define BROWS  1000
#define NFILT  50
#define MPAD   1024
#define NPAD   100096        /* 782*128 */
#define NTILES 782
#define BAND   0.18f
#define GQCAP  (1 << 22)
#define SQCAP  8192

// ---------------- scratch ----------------
__device__ __align__(16) unsigned short g_qhi[MPAD * D];
__device__ __align__(16) unsigned short g_qlo[MPAD * D];
__device__ __align__(16) unsigned short g_bhi[(size_t)NPAD * D];   // [n][k] K-major
__device__ __align__(16) unsigned short g_blo[(size_t)NPAD * D];
__device__ float g_T[BROWS];
__device__ int   g_qcount;
__device__ uint32_t g_queue[2 * GQCAP];                            // {key, s2}

// ---------------- helpers (sm_80-class PTX only) ----------------
__device__ __forceinline__ uint32_t smem_u32(const void* p) {
    uint32_t a;
    asm("{ .reg .u64 t; cvta.to.shared.u64 t, %1; cvt.u32.u64 %0, t; }" : "=r"(a) : "l"(p));
    return a;
}
__device__ __forceinline__ void cp16(uint32_t dst, const void* src) {
    asm volatile("cp.async.cg.shared.global [%0], [%1], 16;" :: "r"(dst), "l"(src));
}
__device__ __forceinline__ void ldm4(uint32_t* r, uint32_t a) {
    asm volatile("ldmatrix.sync.aligned.m8n8.x4.shared.b16 {%0,%1,%2,%3}, [%4];"
                 : "=r"(r[0]), "=r"(r[1]), "=r"(r[2]), "=r"(r[3]) : "r"(a));
}
__device__ __forceinline__ void mma4(float* c, const uint32_t* a, uint32_t b0, uint32_t b1) {
    asm volatile("mma.sync.aligned.m16n8k16.row.col.f32.bf16.bf16.f32 "
                 "{%0,%1,%2,%3}, {%4,%5,%6,%7}, {%8,%9}, {%0,%1,%2,%3};"
                 : "+f"(c[0]), "+f"(c[1]), "+f"(c[2]), "+f"(c[3])
                 : "r"(a[0]), "r"(a[1]), "r"(a[2]), "r"(a[3]), "r"(b0), "r"(b1));
}
__device__ __forceinline__ void split4(const float* x, unsigned int* hiw, unsigned int* low) {
    #pragma unroll
    for (int p = 0; p < 2; p++) {
        unsigned int u0 = __float_as_uint(x[2 * p]);
        unsigned int u1 = __float_as_uint(x[2 * p + 1]);
        hiw[p] = __byte_perm(u0, u1, 0x7632);
        float h0 = __uint_as_float(u0 & 0xFFFF0000u);
        float h1 = __uint_as_float(u1 & 0xFFFF0000u);
        __nv_bfloat162 lp = __floats2bfloat162_rn(x[2 * p] - h0, x[2 * p + 1] - h1);
        low[p] = *(unsigned int*)&lp;
    }
}

// ---------------------------------------------------------------------------
// convert q -> hi/lo bf16 (pad rows zero); resets queue counter
// ---------------------------------------------------------------------------
__global__ void conv_q_kernel(const float* __restrict__ q) {
    int gid  = blockIdx.x * 256 + threadIdx.x;
    if (gid == 0) g_qcount = 0;
    int base = gid * 8;
    if (base >= MPAD * D) return;
    int row = base >> 9;
    float x[8];
    if (row < BROWS) {
        float4 f0 = *(const float4*)(q + base);
        float4 f1 = *(const float4*)(q + base + 4);
        x[0]=f0.x; x[1]=f0.y; x[2]=f0.z; x[3]=f0.w;
        x[4]=f1.x; x[5]=f1.y; x[6]=f1.z; x[7]=f1.w;
    } else {
        #pragma unroll
        for (int i = 0; i < 8; i++) x[i] = 0.f;
    }
    unsigned int hiw[4], low[4];
    split4(x, hiw, low);
    split4(x + 4, hiw + 2, low + 2);
    *(uint4*)(g_qhi + base) = make_uint4(hiw[0], hiw[1], hiw[2], hiw[3]);
    *(uint4*)(g_qlo + base) = make_uint4(low[0], low[1], low[2], low[3]);
}

// ---------------------------------------------------------------------------
// transpose + convert rhs[k][n] fp32 -> g_bhi/g_blo[n][k] bf16 (K-major)
// ---------------------------------------------------------------------------
__global__ void __launch_bounds__(256)
conv_rhsT_kernel(const float* __restrict__ rhs) {
    __shared__ float st[128][68];
    int t  = threadIdx.x;
    int nb = blockIdx.x * 128;
    int kb = blockIdx.y * 64;

    int r  = t >> 5;
    int c4 = t & 31;
    int n0 = nb + c4 * 4;
    #pragma unroll
    for (int rr = 0; rr < 8; rr++) {
        int krow = rr * 8 + r;
        float4 v;
        const float* src = rhs + (size_t)(kb + krow) * NCOLS + n0;
        if (n0 + 3 < NCOLS) {
            v = *(const float4*)src;
        } else {
            v.x = (n0 + 0 < NCOLS) ? src[0] : 0.f;
            v.y = (n0 + 1 < NCOLS) ? src[1] : 0.f;
            v.z = (n0 + 2 < NCOLS) ? src[2] : 0.f;
            v.w = (n0 + 3 < NCOLS) ? src[3] : 0.f;
        }
        st[c4 * 4 + 0][krow] = v.x;
        st[c4 * 4 + 1][krow] = v.y;
        st[c4 * 4 + 2][krow] = v.z;
        st[c4 * 4 + 3][krow] = v.w;
    }
    __syncthreads();

    int n    = t >> 1;
    int koff = (t & 1) * 32;
    unsigned int hiw[16], low[16];
    #pragma unroll
    for (int jj = 0; jj < 8; jj++) {
        float x[4];
        *(float4*)x = *(const float4*)&st[n][koff + jj * 4];
        split4(x, hiw + jj * 2, low + jj * 2);
    }
    size_t o = (size_t)(nb + n) * D + kb + koff;
    #pragma unroll
    for (int s = 0; s < 4; s++) {
        *(uint4*)(g_bhi + o + s * 8) = make_uint4(hiw[s*4], hiw[s*4+1], hiw[s*4+2], hiw[s*4+3]);
        *(uint4*)(g_blo + o + s * 8) = make_uint4(low[s*4], low[s*4+1], low[s*4+2], low[s*4+3]);
    }
}

// ---------------------------------------------------------------------------
// prep: target score t[b] (fp32 q x (b_hi+b_lo), contiguous reads) and
// out[b] = 1 - #(unique filtered j with s_j >= t)
// ---------------------------------------------------------------------------
__global__ void __launch_bounds__(128)
prep_kernel(const float* __restrict__ q,
            const int* __restrict__ fidx, const int* __restrict__ tgt,
            float* __restrict__ out) {
    int b = blockIdx.x;
    __shared__ int   list[NFILT + 1];
    __shared__ float sv[NFILT + 1];
    __shared__ float qs[D];
    int tid = threadIdx.x, wid = tid >> 5, lane = tid & 31;
    for (int k = tid; k < D; k += 128) qs[k] = q[b * D + k];
    if (tid < NFILT)  list[tid]   = min(max(fidx[b * NFILT + tid], 0), NCOLS - 1);
    if (tid == NFILT) list[NFILT] = min(max(tgt[b], 0), NCOLS - 1);
    __syncthreads();
    for (int d = wid; d <= NFILT; d += 4) {
        int j = list[d];
        const uint4* bh = (const uint4*)(g_bhi + (size_t)j * D);
        const uint4* bl = (const uint4*)(g_blo + (size_t)j * D);
        float acc = 0.f;
        #pragma unroll
        for (int v = 0; v < 2; v++) {
            uint4 h = bh[lane * 2 + v];
            uint4 l = bl[lane * 2 + v];
            unsigned int hw[4] = { h.x, h.y, h.z, h.w };
            unsigned int lw[4] = { l.x, l.y, l.z, l.w };
            int k0 = lane * 16 + v * 8;
            #pragma unroll
            for (int w = 0; w < 4; w++) {
                __nv_bfloat162 hb = *(__nv_bfloat162*)&hw[w];
                __nv_bfloat162 lb = *(__nv_bfloat162*)&lw[w];
                float b0 = __bfloat162float(hb.x) + __bfloat162float(lb.x);
                float b1 = __bfloat162float(hb.y) + __bfloat162float(lb.y);
                acc = fmaf(qs[k0 + w * 2 + 0], b0, acc);
                acc = fmaf(qs[k0 + w * 2 + 1], b1, acc);
            }
        }
        #pragma unroll
        for (int o = 16; o; o >>= 1) acc += __shfl_xor_sync(0xFFFFFFFFu, acc, o);
        if (lane == 0) sv[d] = acc;
    }
    __syncthreads();
    if (tid == 0) {
        float tv = sv[NFILT];
        g_T[b] = tv;
        float corr = 0.f;
        for (int i = 0; i <= NFILT; i++) {
            bool uniq = true;
            for (int jj = 0; jj < i; jj++)
                if (list[jj] == list[i]) { uniq = false; break; }
            if (uniq && sv[i] >= tv) corr += 1.f;
        }
        out[b] = 1.f - corr;
    }
}

// ---------------------------------------------------------------------------
// main GEMM: 2 passes (hi*hi + hi*lo), s2 = s_exact - q_lo.b_hi (+eps).
// CTA 128m x 128n, 8 warps (4m x 2n), warp 32x64, OCCUPANCY 2, K-chunk 64,
// 2-stage cp.async, one barrier per chunk. 144B smem row stride.
// Epilogue: s2 >= t+BAND -> count; |s2-t| < BAND -> queue for recheck.
// (unchanged from R12 — converged at tensor ~61%)
// ---------------------------------------------------------------------------
#define A_BYTES    18432                    /* 128 rows * 144B (A hi only) */
#define B_OFF      A_BYTES
#define STG_BYTES  (3 * A_BYTES)            /* A_hi | B_hi | B_lo = 55296 */
#define SMEM_TOT   (2 * STG_BYTES)          /* 110592 */
#define NCHUNK     8

__global__ void __launch_bounds__(256, 2)
gemm_mma_kernel(float* __restrict__ out) {
    extern __shared__ char smem[];
    uint32_t sb = smem_u32(smem);
    const int tid = threadIdx.x, lane = tid & 31, wid = tid >> 5;
    const int warpM = wid & 3, warpN = wid >> 2;   // 4m x 2n
    const int mRow0 = blockIdx.x * 128;
    const int nBase = blockIdx.y * 128;

    float c[2][8][4];
    #pragma unroll
    for (int a = 0; a < 2; a++)
        #pragma unroll
        for (int b = 0; b < 8; b++)
            #pragma unroll
            for (int e = 0; e < 4; e++) c[a][b][e] = 0.f;

    auto load_chunk = [&](int ch, int slot) {
        uint32_t base = sb + slot * STG_BYTES;
        int k0 = ch * 64;
        #pragma unroll
        for (int i = 0; i < 4; i++) {                 // A hi: 1024 16B segs
            int idx = tid + i * 256;
            int r = idx >> 3, seg = idx & 7;
            uint32_t dst = base + r * 144 + seg * 16;
            cp16(dst, g_qhi + (size_t)(mRow0 + r) * D + k0 + seg * 8);
        }
        #pragma unroll
        for (int i = 0; i < 4; i++) {                 // B hi/lo: 1024 segs each
            int idx = tid + i * 256;
            int r = idx >> 3, seg = idx & 7;
            uint32_t dst = base + B_OFF + r * 144 + seg * 16;
            size_t go = (size_t)(nBase + r) * D + k0 + seg * 8;
            cp16(dst,           g_bhi + go);
            cp16(dst + A_BYTES, g_blo + go);
        }
        asm volatile("cp.async.commit_group;" ::: "memory");
    };

    load_chunk(0, 0);

    for (int ch = 0; ch < NCHUNK; ch++) {
        asm volatile("cp.async.wait_group 0;" ::: "memory");
        __syncthreads();
        if (ch + 1 < NCHUNK) load_chunk(ch + 1, (ch + 1) & 1);

        uint32_t Ab = sb + (ch & 1) * STG_BYTES;
        uint32_t Bb = Ab + B_OFF;
        #pragma unroll
        for (int k16 = 0; k16 < 4; k16++) {
            uint32_t AH[2][4];
            {
                int ar   = warpM * 32 + (lane & 15);
                int koff = k16 * 32 + (lane >> 4) * 16;
                #pragma unroll
                for (int mt = 0; mt < 2; mt++)
                    ldm4(AH[mt], Ab + (ar + mt * 16) * 144 + koff);
            }
            uint32_t BH[4][4], BL[4][4];
            {
                int brow  = warpN * 64 + ((lane >> 4) & 1) * 8 + (lane & 7);
                uint32_t boff = k16 * 32 + ((lane >> 3) & 1) * 16;
                #pragma unroll
                for (int nb = 0; nb < 4; nb++) {
                    uint32_t addr = Bb + (brow + nb * 16) * 144 + boff;
                    ldm4(BH[nb], addr);
                    ldm4(BL[nb], addr + A_BYTES);
                }
            }
            #pragma unroll
            for (int p = 0; p < 2; p++) {
                const uint32_t (*Bf)[4] = p ? BL : BH;
                #pragma unroll
                for (int mt = 0; mt < 2; mt++) {
                    #pragma unroll
                    for (int nb = 0; nb < 4; nb++) {
                        mma4(c[mt][2 * nb],     AH[mt], Bf[nb][0], Bf[nb][1]);
                        mma4(c[mt][2 * nb + 1], AH[mt], Bf[nb][2], Bf[nb][3]);
                    }
                }
            }
        }
    }

    // ---- epilogue: banded count + queue ----
    __syncthreads();                         // all smem reads done; reuse smem
    uint32_t* sq = (uint32_t*)smem;
    __shared__ int scnt;
    __shared__ int sbase;
    if (tid == 0) scnt = 0;
    __syncthreads();

    #pragma unroll
    for (int mt = 0; mt < 2; mt++) {
        #pragma unroll
        for (int h = 0; h < 2; h++) {
            int row = mRow0 + warpM * 32 + mt * 16 + h * 8 + (lane >> 2);
            if (row < BROWS) {
                float tv  = g_T[row];
                float tUp = tv + BAND, tDn = tv - BAND;
                float cnt = 0.f;
                #pragma unroll
                for (int nt = 0; nt < 8; nt++) {
                    int col = nBase + warpN * 64 + nt * 8 + (lane & 3) * 2;
                    #pragma unroll
                    for (int e = 0; e < 2; e++) {
                        int cc = col + e;
                        if (cc < NCOLS) {
                            float s2 = c[mt][nt][h * 2 + e];
                            if (s2 >= tUp) cnt += 1.f;
                            else if (s2 > tDn) {
                                uint32_t key = ((uint32_t)row << 17) | (uint32_t)cc;
                                int slot = atomicAdd(&scnt, 1);
                                if (slot < SQCAP) {
                                    sq[2 * slot]     = key;
                                    sq[2 * slot + 1] = __float_as_uint(s2);
                                } else {
                                    int g = atomicAdd(&g_qcount, 1);
                                    if (g < GQCAP) {
                                        g_queue[2 * g]     = key;
                                        g_queue[2 * g + 1] = __float_as_uint(s2);
                                    }
                                }
                            }
                        }
                    }
                }
                cnt += __shfl_xor_sync(0xFFFFFFFFu, cnt, 1);
                cnt += __shfl_xor_sync(0xFFFFFFFFu, cnt, 2);
                if ((lane & 3) == 0 && cnt != 0.f) atomicAdd(out + row, cnt);
            } else {
                __shfl_xor_sync(0xFFFFFFFFu, 0.f, 1);
                __shfl_xor_sync(0xFFFFFFFFu, 0.f, 2);
            }
        }
    }
    __syncthreads();
    if (tid == 0) {
        int n = min(scnt, SQCAP);
        sbase = (n > 0) ? atomicAdd(&g_qcount, n) : 0;
    }
    __syncthreads();
    int n = min(scnt, SQCAP);
    for (int i = tid; i < n; i += 256) {
        int g = sbase + i;
        if (g < GQCAP) {
            g_queue[2 * g]     = sq[2 * i];
            g_queue[2 * g + 1] = sq[2 * i + 1];
        }
    }
}

// ---------------------------------------------------------------------------
// recheck: s_refined = s2 + q_lo . b_hi  (HALF-warp per entry -> 2x MLP)
// ---------------------------------------------------------------------------
__global__ void __launch_bounds__(256)
recheck_kernel(float* __restrict__ out) {
    int gh    = (blockIdx.x * 256 + threadIdx.x) >> 4;   // global half-warp id
    int lane16 = threadIdx.x & 15;
    int total = g_qcount;
    if (total > GQCAP) total = GQCAP;
    int nh = gridDim.x * 16;
    for (int i = gh; i < total; i += nh) {
        uint32_t key = g_queue[2 * i];
        float s2 = __uint_as_float(g_queue[2 * i + 1]);
        int row = (int)(key >> 17), col = (int)(key & 0x1FFFFu);
        const uint4* ql = (const uint4*)(g_qlo + (size_t)row * D) + lane16 * 4;
        const uint4* bh = (const uint4*)(g_bhi + (size_t)col * D) + lane16 * 4;
        float d = 0.f;
        #pragma unroll
        for (int v = 0; v < 4; v++) {
            uint4 a = ql[v];
            uint4 b = bh[v];
            unsigned int aw[4] = { a.x, a.y, a.z, a.w };
            unsigned int bw[4] = { b.x, b.y, b.z, b.w };
            #pragma unroll
            for (int w = 0; w < 4; w++) {
                __nv_bfloat162 qa = *(__nv_bfloat162*)&aw[w];
                __nv_bfloat162 bb = *(__nv_bfloat162*)&bw[w];
                d = fmaf(__bfloat162float(qa.x), __bfloat162float(bb.x), d);
                d = fmaf(__bfloat162float(qa.y), __bfloat162float(bb.y), d);
            }
        }
        #pragma unroll
        for (int o = 8; o; o >>= 1) d += __shfl_xor_sync(0xFFFFFFFFu, d, o);
        if (lane16 == 0 && (s2 + d) >= g_T[row]) atomicAdd(out + row, 1.f);
    }
}

// ---------------------------------------------------------------------------
extern "C" void kernel_launch(void* const* d_in, const int* in_sizes, int n_in,
                              void* d_out, int out_size) {
    const float* q    = nullptr;
    const float* rhs  = nullptr;
    const int*   fidx = nullptr;
    const int*   tgt  = nullptr;
    for (int i = 0; i < n_in; i++) {
        switch (in_sizes[i]) {
            case BROWS * D:     q    = (const float*)d_in[i]; break;
            case D * NCOLS:     rhs  = (const float*)d_in[i]; break;
            case BROWS * NFILT: fidx = (const int*)d_in[i];   break;
            case BROWS:         tgt  = (const int*)d_in[i];   break;
        }
    }
    float* out = (float*)d_out;

    cudaFuncSetAttribute(gemm_mma_kernel,
                         cudaFuncAttributeMaxDynamicSharedMemorySize, SMEM_TOT);

    conv_q_kernel<<<256, 256>>>(q);
    conv_rhsT_kernel<<<dim3(NTILES, D / 64), 256>>>(rhs);
    prep_kernel<<<BROWS, 128>>>(q, fidx, tgt, out);
    gemm_mma_kernel<<<dim3(8, NTILES), 256, SMEM_TOT>>>(out);
    recheck_kernel<<<1184, 256>>>(out);
}